// round 6
// baseline (speedup 1.0000x reference)
#include <cuda_runtime.h>
#include <cuda_fp16.h>
#include <math.h>

#define BB 16
#define CC 3
#define HH 384
#define WW 1280
#define HW (HH * WW)
#define EPSF 1e-7f

// Per-batch fused transform: coord = d * A @ [x,y,1] + tv   (A = K R K^-1, tv = K t)
__device__ float g_A[BB][9];
__device__ float g_tv[BB][3];

// Pair texels: pair[p] = {rgb(p), rgb(p+1 same row, clamped)} as 8 fp16 = 16B.
// 16*384*1280*16B = 125.8 MB static scratch (~L2 capacity).
__device__ uint4 g_pair[(size_t)BB * HW];

__device__ __forceinline__ void compute_mats_one(const float* __restrict__ pose,
                                                 const float* __restrict__ intr,
                                                 int b) {
    float K[9];
#pragma unroll
    for (int i = 0; i < 9; i++) K[i] = intr[b * 9 + i];

    float c00 =  (K[4] * K[8] - K[5] * K[7]);
    float c01 = -(K[3] * K[8] - K[5] * K[6]);
    float c02 =  (K[3] * K[7] - K[4] * K[6]);
    float det = K[0] * c00 + K[1] * c01 + K[2] * c02;
    float id = 1.0f / det;
    float inv[9];
    inv[0] = c00 * id;
    inv[1] = -(K[1] * K[8] - K[2] * K[7]) * id;
    inv[2] =  (K[1] * K[5] - K[2] * K[4]) * id;
    inv[3] = c01 * id;
    inv[4] =  (K[0] * K[8] - K[2] * K[6]) * id;
    inv[5] = -(K[0] * K[5] - K[2] * K[3]) * id;
    inv[6] = c02 * id;
    inv[7] = -(K[0] * K[7] - K[1] * K[6]) * id;
    inv[8] =  (K[0] * K[4] - K[1] * K[3]) * id;

    float ax = pose[b * 6 + 0], ay = pose[b * 6 + 1], az = pose[b * 6 + 2];
    float theta = sqrtf(ax * ax + ay * ay + az * az);
    float ith = 1.0f / (theta + EPSF);
    float x = ax * ith, y = ay * ith, z = az * ith;
    float c = cosf(theta), s = sinf(theta), t = 1.0f - c;
    float R[9];
    R[0] = t * x * x + c;     R[1] = t * x * y - s * z; R[2] = t * z * x + s * y;
    R[3] = t * x * y + s * z; R[4] = t * y * y + c;     R[5] = t * y * z - s * x;
    R[6] = t * z * x - s * y; R[7] = t * y * z + s * x; R[8] = t * z * z + c;

    float KR[9];
#pragma unroll
    for (int i = 0; i < 3; i++)
#pragma unroll
        for (int j = 0; j < 3; j++) {
            float sum = 0.0f;
#pragma unroll
            for (int k = 0; k < 3; k++) sum += K[i * 3 + k] * R[k * 3 + j];
            KR[i * 3 + j] = sum;
        }
#pragma unroll
    for (int i = 0; i < 3; i++)
#pragma unroll
        for (int j = 0; j < 3; j++) {
            float sum = 0.0f;
#pragma unroll
            for (int k = 0; k < 3; k++) sum += KR[i * 3 + k] * inv[k * 3 + j];
            g_A[b][i * 3 + j] = sum;
        }

    float tx = pose[b * 6 + 3], ty = pose[b * 6 + 4], tz = pose[b * 6 + 5];
    g_tv[b][0] = K[0] * tx + K[1] * ty + K[2] * tz;
    g_tv[b][1] = K[3] * tx + K[4] * ty + K[5] * tz;
    g_tv[b][2] = K[6] * tx + K[7] * ty + K[8] * tz;
}

__device__ __forceinline__ unsigned int pack_h2(float a, float b) {
    __half2 h = __floats2half2_rn(a, b);
    return *reinterpret_cast<unsigned int*>(&h);
}

// CHW fp32 -> fp16 pair-texel pack (4 px/thread) + fused mat precompute.
// Each warp covers 128 contiguous px of one row (1280 % 128 == 0).
__global__ void __launch_bounds__(256)
pack_pair_kernel(const float* __restrict__ img,
                 const float* __restrict__ pose,
                 const float* __restrict__ intr) {
    if (blockIdx.x == 0 && threadIdx.x < BB) {
        compute_mats_one(pose, intr, threadIdx.x);
    }

    int tid = blockIdx.x * blockDim.x + threadIdx.x;
    int p = tid * 4;
    if (p >= BB * HW) return;

    int b = p / HW;
    int rem = p - b * HW;
    int x = rem % WW;                       // multiple of 4
    const float* plane = img + (size_t)b * CC * HW;

    float4 r  = __ldcs(reinterpret_cast<const float4*>(plane + rem));
    float4 g  = __ldcs(reinterpret_cast<const float4*>(plane + HW + rem));
    float4 bl = __ldcs(reinterpret_cast<const float4*>(plane + 2 * HW + rem));

    // neighbor pixel (x+4) from next lane; lane 31 handles edge
    float rn = __shfl_down_sync(0xffffffffu, r.x, 1);
    float gn = __shfl_down_sync(0xffffffffu, g.x, 1);
    float bn = __shfl_down_sync(0xffffffffu, bl.x, 1);
    if ((threadIdx.x & 31) == 31) {
        if (x + 3 == WW - 1) {              // row end: duplicate last pixel
            rn = r.w; gn = g.w; bn = bl.w;
        } else {                            // same row, next warp's first pixel
            rn = __ldcs(plane + rem + 4);
            gn = __ldcs(plane + HW + rem + 4);
            bn = __ldcs(plane + 2 * HW + rem + 4);
        }
    }

    float rr[5] = {r.x, r.y, r.z, r.w, rn};
    float gg[5] = {g.x, g.y, g.z, g.w, gn};
    float bb[5] = {bl.x, bl.y, bl.z, bl.w, bn};

    uint4* dst = &g_pair[(size_t)p];
#pragma unroll
    for (int i = 0; i < 4; i++) {
        uint4 u;
        u.x = pack_h2(rr[i],     gg[i]);
        u.y = pack_h2(bb[i],     0.0f);
        u.z = pack_h2(rr[i + 1], gg[i + 1]);
        u.w = pack_h2(bb[i + 1], 0.0f);
        dst[i] = u;
    }
}

// One thread = 2 horizontally adjacent pixels; 2 LDG.128 gathers per pixel
// (each pair texel provides BOTH x-taps of one row).
__global__ void __launch_bounds__(256, 4)
warp_sample_kernel(const float* __restrict__ depth,
                   float* __restrict__ out) {
    int tid = blockIdx.x * blockDim.x + threadIdx.x;
    int pix0 = tid * 2;
    if (pix0 >= BB * HW) return;

    int b = pix0 / HW;
    int rem = pix0 - b * HW;          // even; both pixels on the same row
    int h = rem / WW;
    int w = rem - h * WW;

    float a0 = g_A[b][0], a1 = g_A[b][1], a2 = g_A[b][2];
    float a3 = g_A[b][3], a4 = g_A[b][4], a5 = g_A[b][5];
    float a6 = g_A[b][6], a7 = g_A[b][7], a8 = g_A[b][8];
    float t0 = g_tv[b][0], t1 = g_tv[b][1], t2 = g_tv[b][2];

    float2 d2 = __ldcs(reinterpret_cast<const float2*>(depth + pix0));

    float fy = (float)h;
    float rx = a1 * fy + a2;
    float ry = a4 * fy + a5;
    float rz = a7 * fy + a8;

    const uint4* src = g_pair + (size_t)b * HW;

    float vrA = 0.0f, vgA = 0.0f, vbA = 0.0f;
    float vrB = 0.0f, vgB = 0.0f, vbB = 0.0f;

#pragma unroll
    for (int p = 0; p < 2; p++) {
        float fx = (float)(w + p);
        float d  = (p == 0) ? d2.x : d2.y;
        float X = d * (a0 * fx + rx) + t0;
        float Y = d * (a3 * fx + ry) + t1;
        float Z = d * (a6 * fx + rz) + t2 + EPSF;

        float xs = __fdividef(X, Z);
        float ys = __fdividef(Y, Z);

        float x0f = floorf(xs), y0f = floorf(ys);
        float x1f = x0f + 1.0f, y1f = y0f + 1.0f;
        float wx1 = xs - x0f, wx0 = 1.0f - wx1;
        float wy1 = ys - y0f, wy0 = 1.0f - wy1;

        // in-bounds masks on UNCLIPPED coords (reference semantics)
        float ibx0 = (x0f >= 0.0f && x0f <= (float)(WW - 1)) ? 1.0f : 0.0f;
        float ibx1 = (x1f >= 0.0f && x1f <= (float)(WW - 1)) ? 1.0f : 0.0f;
        float iby0 = (y0f >= 0.0f && y0f <= (float)(HH - 1)) ? 1.0f : 0.0f;
        float iby1 = (y1f >= 0.0f && y1f <= (float)(HH - 1)) ? 1.0f : 0.0f;

        int xb  = (int)fminf(fmaxf(x0f, 0.0f), (float)(WW - 1));
        int yc0 = (int)fminf(fmaxf(y0f, 0.0f), (float)(HH - 1));
        int yc1 = (int)fminf(fmaxf(y1f, 0.0f), (float)(HH - 1));
        bool left = (x0f < 0.0f);   // x1 clamps to 0 -> use slot 0 for tap B

        float w00 = wx0 * wy0 * ibx0 * iby0;
        float w10 = wx1 * wy0 * ibx1 * iby0;
        float w01 = wx0 * wy1 * ibx0 * iby1;
        float w11 = wx1 * wy1 * ibx1 * iby1;

        uint4 u0 = __ldg(src + yc0 * WW + xb);   // row y0: taps (x0, x1)
        uint4 u1 = __ldg(src + yc1 * WW + xb);   // row y1: taps (x0, x1)

        unsigned int b0x = left ? u0.x : u0.z, b0y = left ? u0.y : u0.w;
        unsigned int b1x = left ? u1.x : u1.z, b1y = left ? u1.y : u1.w;

        float2 rgA0 = __half22float2(*reinterpret_cast<__half2*>(&u0.x));
        float  bA0  = __low2float(*reinterpret_cast<__half2*>(&u0.y));
        float2 rgB0 = __half22float2(*reinterpret_cast<__half2*>(&b0x));
        float  bB0  = __low2float(*reinterpret_cast<__half2*>(&b0y));
        float2 rgA1 = __half22float2(*reinterpret_cast<__half2*>(&u1.x));
        float  bA1  = __low2float(*reinterpret_cast<__half2*>(&u1.y));
        float2 rgB1 = __half22float2(*reinterpret_cast<__half2*>(&b1x));
        float  bB1  = __low2float(*reinterpret_cast<__half2*>(&b1y));

        float vr = w00 * rgA0.x + w10 * rgB0.x + w01 * rgA1.x + w11 * rgB1.x;
        float vg = w00 * rgA0.y + w10 * rgB0.y + w01 * rgA1.y + w11 * rgB1.y;
        float vb = w00 * bA0    + w10 * bB0    + w01 * bA1    + w11 * bB1;

        if (p == 0) { vrA = vr; vgA = vg; vbA = vb; }
        else        { vrB = vr; vgB = vg; vbB = vb; }
    }

    size_t base = (size_t)b * CC * HW + rem;
    __stcs(reinterpret_cast<float2*>(out + base),          make_float2(vrA, vrB));
    __stcs(reinterpret_cast<float2*>(out + base + HW),     make_float2(vgA, vgB));
    __stcs(reinterpret_cast<float2*>(out + base + 2 * HW), make_float2(vbA, vbB));
}

extern "C" void kernel_launch(void* const* d_in, const int* in_sizes, int n_in,
                              void* d_out, int out_size) {
    const float* source_image = (const float*)d_in[0];
    const float* depth_map    = (const float*)d_in[1];
    const float* pose         = (const float*)d_in[2];
    const float* intrinsic    = (const float*)d_in[3];
    float* out = (float*)d_out;

    const int threads = 256;

    const int quad_threads = BB * HW / 4;
    pack_pair_kernel<<<(quad_threads + threads - 1) / threads, threads>>>(
        source_image, pose, intrinsic);

    const int pair_threads = BB * HW / 2;
    warp_sample_kernel<<<(pair_threads + threads - 1) / threads, threads>>>(
        depth_map, out);
}